// round 8
// baseline (speedup 1.0000x reference)
#include <cuda_runtime.h>
#include <cuda_bf16.h>

// NormalsRenderer: B=512, N=512.
// out[b] = normalize( sum_i acc_i * n_i ),  acc_i = sum_{j!=i} exp(-acos(clip(<n_i,n_j>)))
// Identities (uniform positive scales cancel under the final normalize):
//   - division by max(new_weights) dropped; exp(-acos d) = const * exp(asin d)
//   - u = sat(1-|d|);  asin(|d|)*log2e = LHPI + sqrt(u)*Q(u)  (cubic Q)
//   - w = exp2( copysign( LHPI + sqrt(u)*Q(u), d ) )
// Tile scheme: rows in 16 groups of 32; upper-tri tiles (g1<=g2) computed once.
// In a tile, lane l keeps i-row g1*32+l in regs and a j-normal in regs; skewed
// schedule: at step jj lane l handles column (l+jj)&31. After each step the j-regs
// AND a traveling column-accumulator rotate one lane via shfl.idx — column sums
// build up entirely in registers (zero smem bytes in the hot loop; the smem
// crossbar was the measured 39us floor of the previous design). Diagonal tiles
// skip step 0 (== the i==j diagonal) instead of predicating.
// Warp W owns row-groups {W, 15-W}: 17 tiles each, perfectly balanced.
// 2 CTAs per batch (grid 1024, 128 thr); per-warp smem flush arrays (race-free),
// cross-CTA merge via atomic counter (second finisher normalizes + writes).

#define NPTS 512
#define TPB  128

typedef unsigned int uint;

// -log2(e) * p_AS(1-u) re-expanded in u, and log2(e)*pi/2
#define Q0f (-2.0401824f)
#define Q1f (-0.17280645f)
#define Q2f (-0.026074023f)
#define Q3f (-0.027020667f)
#define LHPIf (2.2661800709f)

__device__ float g_stage[1024][3];   // per-CTA partial weighted sums
__device__ int   g_cnt[512];         // per-batch arrival counters (reset to 0 each use)

__device__ __forceinline__ float sqrta(float x) {
    float r; asm("sqrt.approx.f32 %0, %1;" : "=f"(r) : "f"(x)); return r;
}
__device__ __forceinline__ float ex2a(float x) {
    float r; asm("ex2.approx.f32 %0, %1;" : "=f"(r) : "f"(x)); return r;
}

// w(d) = exp2( copysign( LHPI + sqrt(u)*Q(u), d ) ),  u = sat(1-|d|)
__device__ __forceinline__ float pair_w(float xi, float yi, float zi,
                                        float jx, float jy, float jz)
{
    float d = fmaf(zi, jz, fmaf(yi, jy, xi * jx));
    float u = __saturatef(1.0f - fabsf(d));
    float s = sqrta(u);
    float p = fmaf(u, Q3f, Q2f);
    p = fmaf(u, p, Q1f);
    p = fmaf(u, p, Q0f);
    float g = fmaf(s, p, LHPIf);
    uint  e = __float_as_uint(g) | (__float_as_uint(d) & 0x80000000u);
    return ex2a(__uint_as_float(e));
}

__global__ __launch_bounds__(TPB, 7)
void normals_tile_kernel(const float* __restrict__ normals,
                         float* __restrict__ out)
{
    __shared__ float4 sn4[NPTS];          // 8 KB: (x,y,z,0) per row
    __shared__ float  rowaccW[4][NPTS];   // 8 KB: per-warp row accumulators
    __shared__ float  sred[3][4];

    const int b    = blockIdx.x >> 1;
    const int half = blockIdx.x & 1;
    const int t    = threadIdx.x;         // 0..127
    const int lane = t & 31;
    const int wl   = t >> 5;              // warp in CTA: 0..3

    const float* base = normals + (size_t)b * NPTS * 3;
    #pragma unroll
    for (int r = t; r < NPTS; r += TPB)
        sn4[r] = make_float4(base[r * 3 + 0], base[r * 3 + 1], base[r * 3 + 2], 0.0f);
    #pragma unroll
    for (int idx = t; idx < 4 * NPTS; idx += TPB)
        ((float*)rowaccW)[idx] = 0.0f;
    __syncthreads();

    const int W    = half * 4 + wl;       // global warp id 0..7
    const int srcp = (lane + 1) & 31;     // rotation source lane

    // Process one segment: row-group g1 versus all g2 in [g1, 15].
    #define SEGMENT(G1)                                                            \
    {                                                                              \
        const int g1_ = (G1);                                                      \
        const float4 ni = sn4[g1_ * 32 + lane];                                    \
        const float xi = ni.x, yi = ni.y, zi = ni.z;                               \
        float rowacc = 0.0f;                                                       \
        /* diagonal tile: start j-regs at own column, rotate once (skips i==j) */  \
        {                                                                          \
            float jx = __shfl_sync(0xffffffffu, xi, srcp);                         \
            float jy = __shfl_sync(0xffffffffu, yi, srcp);                         \
            float jz = __shfl_sync(0xffffffffu, zi, srcp);                         \
            _Pragma("unroll")                                                      \
            for (int jj = 1; jj < 32; ++jj) {                                      \
                rowacc += pair_w(xi, yi, zi, jx, jy, jz);                          \
                jx = __shfl_sync(0xffffffffu, jx, srcp);                           \
                jy = __shfl_sync(0xffffffffu, jy, srcp);                           \
                jz = __shfl_sync(0xffffffffu, jz, srcp);                           \
            }                                                                      \
        }                                                                          \
        for (int g2 = g1_ + 1; g2 < 16; ++g2) {                                    \
            const float4 nj = sn4[g2 * 32 + lane];                                 \
            float jx = nj.x, jy = nj.y, jz = nj.z;                                 \
            float colacc = 0.0f;                                                   \
            _Pragma("unroll")                                                      \
            for (int jj = 0; jj < 32; ++jj) {                                      \
                float w = pair_w(xi, yi, zi, jx, jy, jz);                          \
                rowacc += w;                                                       \
                colacc += w;                                                       \
                colacc = __shfl_sync(0xffffffffu, colacc, srcp);                   \
                jx = __shfl_sync(0xffffffffu, jx, srcp);                           \
                jy = __shfl_sync(0xffffffffu, jy, srcp);                           \
                jz = __shfl_sync(0xffffffffu, jz, srcp);                           \
            }                                                                      \
            rowaccW[wl][g2 * 32 + lane] += colacc;   /* this warp's array only */  \
        }                                                                          \
        rowaccW[wl][g1_ * 32 + lane] += rowacc;                                    \
    }

    SEGMENT(W);
    SEGMENT(15 - W);

    __syncthreads();

    // Per-thread weighted sum over 4 rows (t, t+128, t+256, t+384).
    float vx = 0.0f, vy = 0.0f, vz = 0.0f;
    #pragma unroll
    for (int r = t; r < NPTS; r += TPB) {
        float wsum = (rowaccW[0][r] + rowaccW[1][r])
                   + (rowaccW[2][r] + rowaccW[3][r]);
        float4 n = sn4[r];
        vx = fmaf(wsum, n.x, vx);
        vy = fmaf(wsum, n.y, vy);
        vz = fmaf(wsum, n.z, vz);
    }

    #pragma unroll
    for (int s = 16; s >= 1; s >>= 1) {
        vx += __shfl_down_sync(0xffffffffu, vx, s);
        vy += __shfl_down_sync(0xffffffffu, vy, s);
        vz += __shfl_down_sync(0xffffffffu, vz, s);
    }
    if (lane == 0) { sred[0][wl] = vx; sred[1][wl] = vy; sred[2][wl] = vz; }
    __syncthreads();

    if (t == 0) {
        float rx = (sred[0][0] + sred[0][1]) + (sred[0][2] + sred[0][3]);
        float ry = (sred[1][0] + sred[1][1]) + (sred[1][2] + sred[1][3]);
        float rz = (sred[2][0] + sred[2][1]) + (sred[2][2] + sred[2][3]);
        g_stage[blockIdx.x][0] = rx;
        g_stage[blockIdx.x][1] = ry;
        g_stage[blockIdx.x][2] = rz;
        __threadfence();
        int old = atomicAdd(&g_cnt[b], 1);
        if (old == 1) {   // second arrival: combine + normalize + write, reset counter
            __threadfence();
            const int other = blockIdx.x ^ 1;
            rx += g_stage[other][0];
            ry += g_stage[other][1];
            rz += g_stage[other][2];
            float ss  = fmaf(rx, rx, fmaf(ry, ry, rz * rz));
            float inv = rsqrtf(fmaxf(ss, 1e-20f));
            out[b * 3 + 0] = rx * inv;
            out[b * 3 + 1] = ry * inv;
            out[b * 3 + 2] = rz * inv;
            g_cnt[b] = 0;   // deterministic state for graph replay
        }
    }
}

extern "C" void kernel_launch(void* const* d_in, const int* in_sizes, int n_in,
                              void* d_out, int out_size)
{
    const float* normals = (const float*)d_in[0];  // [512, 512, 3] f32
    // d_in[1] = weights: unused by the reference math.
    float* out = (float*)d_out;                    // [512, 3] f32

    normals_tile_kernel<<<1024, TPB>>>(normals, out);
}

// round 9
// speedup vs baseline: 1.1628x; 1.1628x over previous
#include <cuda_runtime.h>
#include <cuda_bf16.h>

// NormalsRenderer: B=512, N=512.
// out[b] = normalize( sum_i acc_i * n_i ),  acc_i = sum_{j!=i} exp(-acos(clip(<n_i,n_j>)))
// Identities (uniform positive scales cancel under the final normalize):
//   - division by max(new_weights) dropped; exp(-acos d) = const * exp(asin d)
//   - u = sat(1-|d|);  asin(|d|)*log2e = LHPI + sqrt(u)*Q(u)  (cubic Q)
//   - w = exp2( copysign( LHPI + sqrt(u)*Q(u), d ) )
// 512 rows = 16 groups of 32. Unordered group-tiles (g1<=g2): 136, covered by 40
// chunks of (<=4 i-groups x 1 j-group), 5 chunks per warp, 8 warps per batch —
// exactly 17344 pair-evals per warp. In a chunk, lane l holds one i-row from each
// of up to 4 groups IN REGISTERS; the j-row rotates through the warp via shfl
// (3 shfls) with a traveling column-accumulator (1 shfl) — 4 shfls serve up to 4
// evals (R8's 4 shfls/eval was the measured 62us SHFL wall; this is 1/eval).
// Diagonal group in a chunk: step 0 (i==j) skipped, excluded from colacc (its
// tile covers both directions of each unordered pair via rowacc alone).
// 2 CTAs per batch (grid 1024, 128 thr); per-warp smem row accumulators, CTA
// reduce, cross-CTA merge via atomic counter (second finisher normalizes).

#define NPTS 512
#define TPB  128

typedef unsigned long long ull;
typedef unsigned int uint;

// -log2(e) * p_AS(1-u) re-expanded in u, and log2(e)*pi/2
#define Q0f (-2.0401824f)
#define Q1f (-0.17280645f)
#define Q2f (-0.026074023f)
#define Q3f (-0.027020667f)
#define LHPIf (2.2661800709f)

__device__ float g_stage[1024][3];
__device__ int   g_cnt[512];

// chunk tables: warp W (0..7) runs 5 chunks (gj, gi_base, ng); diag iff gj-gib==ng-1
__constant__ signed char c_gj[8][5] = {
    {3,4,5,6,0}, {7,7,8,8,4}, {9,9,10,10,8}, {11,11,11,12,12},
    {12,12,13,2,1}, {13,13,14,6,5}, {14,14,15,10,9}, {15,15,15,14,13}};
__constant__ signed char c_gib[8][5] = {
    {0,0,0,0,0}, {0,4,0,4,4}, {0,4,0,4,8}, {0,4,8,0,12},
    {4,8,0,0,0}, {4,8,0,4,4}, {4,8,0,8,8}, {4,8,12,12,12}};
__constant__ signed char c_ng[8][5] = {
    {4,4,4,4,1}, {4,4,4,4,1}, {4,4,4,4,1}, {4,4,4,4,1},
    {4,4,4,3,2}, {4,4,4,3,2}, {4,4,4,3,2}, {4,4,4,3,2}};

__device__ __forceinline__ ull pack2(float lo, float hi) {
    ull r; asm("mov.b64 %0, {%1, %2};" : "=l"(r) : "f"(lo), "f"(hi)); return r;
}
__device__ __forceinline__ void unpack2(ull v, float& lo, float& hi) {
    asm("mov.b64 {%0, %1}, %2;" : "=f"(lo), "=f"(hi) : "l"(v));
}
__device__ __forceinline__ ull fma2(ull a, ull b, ull c) {
    ull d; asm("fma.rn.f32x2 %0, %1, %2, %3;" : "=l"(d) : "l"(a), "l"(b), "l"(c)); return d;
}
__device__ __forceinline__ ull mul2(ull a, ull b) {
    ull d; asm("mul.rn.f32x2 %0, %1, %2;" : "=l"(d) : "l"(a), "l"(b)); return d;
}
__device__ __forceinline__ ull add2(ull a, ull b) {
    ull d; asm("add.rn.f32x2 %0, %1, %2;" : "=l"(d) : "l"(a), "l"(b)); return d;
}
__device__ __forceinline__ float sqrta(float x) {
    float r; asm("sqrt.approx.f32 %0, %1;" : "=f"(r) : "f"(x)); return r;
}
__device__ __forceinline__ float ex2a(float x) {
    float r; asm("ex2.approx.f32 %0, %1;" : "=f"(r) : "f"(x)); return r;
}

// packed 2-eval pipeline (identical math to the 57.9us kernel)
__device__ __forceinline__ ull eval2(ull xi2, ull yi2, ull zi2,
                                     ull jx2, ull jy2, ull jz2)
{
    const ull q3v = pack2(Q3f, Q3f), q2v = pack2(Q2f, Q2f);
    const ull q1v = pack2(Q1f, Q1f), q0v = pack2(Q0f, Q0f);
    const ull lh2 = pack2(LHPIf, LHPIf);
    ull d2 = fma2(zi2, jz2, fma2(yi2, jy2, mul2(xi2, jx2)));
    float da, db; unpack2(d2, da, db);
    float ua = __saturatef(1.0f - fabsf(da));
    float ub = __saturatef(1.0f - fabsf(db));
    float sa = sqrta(ua), sb = sqrta(ub);
    ull u2 = pack2(ua, ub);
    ull p2 = fma2(u2, q3v, q2v);
    p2 = fma2(u2, p2, q1v);
    p2 = fma2(u2, p2, q0v);
    ull g2 = fma2(pack2(sa, sb), p2, lh2);
    float ga, gb; unpack2(g2, ga, gb);
    uint ea = __float_as_uint(ga) | (__float_as_uint(da) & 0x80000000u);
    uint eb = __float_as_uint(gb) | (__float_as_uint(db) & 0x80000000u);
    return pack2(ex2a(__uint_as_float(ea)), ex2a(__uint_as_float(eb)));
}

__device__ __forceinline__ float eval1(float xi, float yi, float zi,
                                       float jx, float jy, float jz)
{
    float d = fmaf(zi, jz, fmaf(yi, jy, xi * jx));
    float u = __saturatef(1.0f - fabsf(d));
    float s = sqrta(u);
    float p = fmaf(u, Q3f, Q2f);
    p = fmaf(u, p, Q1f);
    p = fmaf(u, p, Q0f);
    float g = fmaf(s, p, LHPIf);
    uint  e = __float_as_uint(g) | (__float_as_uint(d) & 0x80000000u);
    return ex2a(__uint_as_float(e));
}

template<int NG, bool DIAG>
__device__ __forceinline__ void process_chunk(const float4* __restrict__ sn4,
                                              float* __restrict__ raw,   // this warp's 512-float row acc
                                              int gj, int gib, int lane, int srcp)
{
    // i-rows in registers
    float4 n0 = sn4[(gib + 0) * 32 + lane];
    float4 n1, n2, n3;
    if (NG >= 2) n1 = sn4[(gib + 1) * 32 + lane];
    if (NG >= 3) n2 = sn4[(gib + 2) * 32 + lane];
    if (NG >= 4) n3 = sn4[(gib + 3) * 32 + lane];

    ull xi01 = 0, yi01 = 0, zi01 = 0, xi23 = 0, yi23 = 0, zi23 = 0;
    float xs = 0, ys = 0, zs = 0;   // scalar lane: q0 (NG==1) or q2 (NG==3)
    if (NG >= 2) { xi01 = pack2(n0.x, n1.x); yi01 = pack2(n0.y, n1.y); zi01 = pack2(n0.z, n1.z); }
    if (NG == 4) { xi23 = pack2(n2.x, n3.x); yi23 = pack2(n2.y, n3.y); zi23 = pack2(n2.z, n3.z); }
    if (NG == 3) { xs = n2.x; ys = n2.y; zs = n2.z; }
    if (NG == 1) { xs = n0.x; ys = n0.y; zs = n0.z; }

    float4 nj = sn4[gj * 32 + lane];
    float jx = nj.x, jy = nj.y, jz = nj.z;

    ull   ra01 = 0, ra23 = 0;
    float ras = 0.0f, colacc = 0.0f;
    constexpr bool HAS_COL = !(NG == 1 && DIAG);

    #define CHUNK_STEP(S0)                                                         \
    {                                                                              \
        ull jxx = pack2(jx, jx), jyy = pack2(jy, jy), jzz = pack2(jz, jz);         \
        ull w01 = 0, w23 = 0; float ws = 0.0f;                                     \
        if (NG >= 2) w01 = eval2(xi01, yi01, zi01, jxx, jyy, jzz);                 \
        if (NG == 4) w23 = eval2(xi23, yi23, zi23, jxx, jyy, jzz);                 \
        if (NG == 3 || NG == 1) ws = eval1(xs, ys, zs, jx, jy, jz);                \
        float w01l = 0, w01h = 0, w23l = 0, w23h = 0;                              \
        if (NG >= 2) unpack2(w01, w01l, w01h);                                     \
        if (NG == 4) unpack2(w23, w23l, w23h);                                     \
        /* row accumulation (diag group = q NG-1: zero its w at step 0) */         \
        if (NG >= 2) ra01 = add2(ra01, (S0 && DIAG && NG == 2)                     \
                                           ? pack2(w01l, 0.0f) : w01);             \
        if (NG == 4) ra23 = add2(ra23, (S0 && DIAG) ? pack2(w23l, 0.0f) : w23);    \
        if (NG == 3 || NG == 1) ras += (S0 && DIAG) ? 0.0f : ws;                   \
        /* column accumulation: diag group excluded at ALL steps */                \
        if (HAS_COL) {                                                             \
            float cs;                                                              \
            if (NG == 4)      cs = (w01l + w01h) + (DIAG ? w23l : (w23l + w23h));  \
            else if (NG == 3) cs = (w01l + w01h) + (DIAG ? 0.0f : ws);             \
            else if (NG == 2) cs = DIAG ? w01l : (w01l + w01h);                    \
            else              cs = ws;                                             \
            colacc += cs;                                                          \
            colacc = __shfl_sync(0xffffffffu, colacc, srcp);                       \
        }                                                                          \
        jx = __shfl_sync(0xffffffffu, jx, srcp);                                   \
        jy = __shfl_sync(0xffffffffu, jy, srcp);                                   \
        jz = __shfl_sync(0xffffffffu, jz, srcp);                                   \
    }

    CHUNK_STEP(true);                       // s = 0 (diag-masked)
    #pragma unroll 4
    for (int s = 1; s < 32; ++s) CHUNK_STEP(false);
    #undef CHUNK_STEP

    // flush row sums (this warp's private array — no races)
    {
        float r0 = 0, r1 = 0, r2v = 0, r3v = 0;
        if (NG >= 2) unpack2(ra01, r0, r1); 
        if (NG == 4) unpack2(ra23, r2v, r3v);
        if (NG == 3) r2v = ras;
        if (NG == 1) r0 = ras;
        raw[(gib + 0) * 32 + lane] += r0;
        if (NG >= 2) raw[(gib + 1) * 32 + lane] += r1;
        if (NG >= 3) raw[(gib + 2) * 32 + lane] += r2v;
        if (NG >= 4) raw[(gib + 3) * 32 + lane] += r3v;
        if (HAS_COL) raw[gj * 32 + lane] += colacc;   // colacc aligned after 32 rotations
    }
}

__global__ __launch_bounds__(TPB, 8)
void normals_chunk_kernel(const float* __restrict__ normals,
                          float* __restrict__ out)
{
    __shared__ float4 sn4[NPTS];          // 8 KB
    __shared__ float  rowaccW[4][NPTS];   // 8 KB per-warp row accumulators
    __shared__ float  sred[3][4];

    const int b    = blockIdx.x >> 1;
    const int half = blockIdx.x & 1;
    const int t    = threadIdx.x;
    const int lane = t & 31;
    const int wl   = t >> 5;
    const int srcp = (lane + 1) & 31;

    const float* base = normals + (size_t)b * NPTS * 3;
    #pragma unroll
    for (int r = t; r < NPTS; r += TPB)
        sn4[r] = make_float4(base[r * 3 + 0], base[r * 3 + 1], base[r * 3 + 2], 0.0f);
    #pragma unroll
    for (int idx = t; idx < 4 * NPTS; idx += TPB)
        ((float*)rowaccW)[idx] = 0.0f;
    __syncthreads();

    const int W = half * 4 + wl;          // global warp id 0..7
    float* raw = rowaccW[wl];

    #pragma unroll 1
    for (int c = 0; c < 5; ++c) {
        const int gj  = c_gj[W][c];
        const int gib = c_gib[W][c];
        const int ng  = c_ng[W][c];
        const bool dg = (gj - gib == ng - 1);
        if (ng == 4) {
            if (dg) process_chunk<4, true >(sn4, raw, gj, gib, lane, srcp);
            else    process_chunk<4, false>(sn4, raw, gj, gib, lane, srcp);
        } else if (ng == 3) {
            process_chunk<3, true>(sn4, raw, gj, gib, lane, srcp);
        } else if (ng == 2) {
            process_chunk<2, true>(sn4, raw, gj, gib, lane, srcp);
        } else {
            process_chunk<1, true>(sn4, raw, gj, gib, lane, srcp);
        }
    }
    __syncthreads();

    // weighted sum over rows handled by this thread
    float vx = 0.0f, vy = 0.0f, vz = 0.0f;
    #pragma unroll
    for (int r = t; r < NPTS; r += TPB) {
        float wsum = (rowaccW[0][r] + rowaccW[1][r])
                   + (rowaccW[2][r] + rowaccW[3][r]);
        float4 n = sn4[r];
        vx = fmaf(wsum, n.x, vx);
        vy = fmaf(wsum, n.y, vy);
        vz = fmaf(wsum, n.z, vz);
    }

    #pragma unroll
    for (int s = 16; s >= 1; s >>= 1) {
        vx += __shfl_down_sync(0xffffffffu, vx, s);
        vy += __shfl_down_sync(0xffffffffu, vy, s);
        vz += __shfl_down_sync(0xffffffffu, vz, s);
    }
    if (lane == 0) { sred[0][wl] = vx; sred[1][wl] = vy; sred[2][wl] = vz; }
    __syncthreads();

    if (t == 0) {
        float rx = (sred[0][0] + sred[0][1]) + (sred[0][2] + sred[0][3]);
        float ry = (sred[1][0] + sred[1][1]) + (sred[1][2] + sred[1][3]);
        float rz = (sred[2][0] + sred[2][1]) + (sred[2][2] + sred[2][3]);
        g_stage[blockIdx.x][0] = rx;
        g_stage[blockIdx.x][1] = ry;
        g_stage[blockIdx.x][2] = rz;
        __threadfence();
        int old = atomicAdd(&g_cnt[b], 1);
        if (old == 1) {
            __threadfence();
            const int other = blockIdx.x ^ 1;
            rx += g_stage[other][0];
            ry += g_stage[other][1];
            rz += g_stage[other][2];
            float ss  = fmaf(rx, rx, fmaf(ry, ry, rz * rz));
            float inv = rsqrtf(fmaxf(ss, 1e-20f));
            out[b * 3 + 0] = rx * inv;
            out[b * 3 + 1] = ry * inv;
            out[b * 3 + 2] = rz * inv;
            g_cnt[b] = 0;   // deterministic state for graph replay
        }
    }
}

extern "C" void kernel_launch(void* const* d_in, const int* in_sizes, int n_in,
                              void* d_out, int out_size)
{
    const float* normals = (const float*)d_in[0];  // [512, 512, 3] f32
    // d_in[1] = weights: unused by the reference math.
    float* out = (float*)d_out;                    // [512, 3] f32

    normals_chunk_kernel<<<1024, TPB>>>(normals, out);
}